// round 5
// baseline (speedup 1.0000x reference)
#include <cuda_runtime.h>

// WavUnPacking: inverse Haar DWT (db1, per-2x2 butterfly + interleave).
// x: (B=8, C=256, H=128, W=128) fp32 -> out: (B=8, C4=64, 2H=256, 2W=256) fp32
//
// R5: R4's dense-store mapping + 2 input rows per thread.
//  - Thread (bc, r, j): loads float2 at (row 2r, col 2j) and (row 2r+1, col 2j)
//    from each subband -> 8 front-batched dense LDG.64 (MLP_p1=8).
//  - Stores 4 fully-dense STG.128 (output rows 4r..4r+3, f4 column j).
//  - Regs ~36-40 -> occupancy stays ~75% (unlike R2's 44-reg version).

static constexpr int B  = 8;
static constexpr int C4 = 64;   // output channels
static constexpr int H  = 128;
static constexpr int R  = H / 2; // input row pairs = 64
static constexpr int J  = 64;   // output float4 columns per row

__device__ __forceinline__ void butterfly2(const float2& ll, const float2& lh,
                                           const float2& hl, const float2& hh,
                                           float4& top, float4& bot)
{
    float a, b, c, d;
    a = ll.x; b = lh.x; c = hl.x; d = hh.x;
    top.x = 0.5f*(a+b+c+d);  top.y = 0.5f*(a+b-c-d);
    bot.x = 0.5f*(a-b+c-d);  bot.y = 0.5f*(a-b-c+d);
    a = ll.y; b = lh.y; c = hl.y; d = hh.y;
    top.z = 0.5f*(a+b+c+d);  top.w = 0.5f*(a+b-c-d);
    bot.z = 0.5f*(a-b+c-d);  bot.w = 0.5f*(a-b-c+d);
}

__global__ void __launch_bounds__(256)
wav_unpack_kernel(const float2* __restrict__ x, float4* __restrict__ out)
{
    int idx = blockIdx.x * blockDim.x + threadIdx.x;
    // idx layout: [bc (512)][r (64)][j (64)]
    int j  = idx & (J - 1);           // 0..63 output f4 column
    int r  = (idx >> 6) & (R - 1);    // 0..63 input row pair
    int bc = idx >> 12;               // 0..511
    int b  = bc >> 6;
    int c  = bc & (C4 - 1);

    // input as float2: per-channel plane = 128 rows * 64 float2
    const int plane2 = H * 64;
    int base = ((b * 256 + c) * H + 2 * r) * 64 + j;  // row 2r, float2 col j
    const int cs = C4 * plane2;                       // subband stride (float2)

    // 8 front-batched independent dense loads (rows 2r and 2r+1, 4 subbands)
    float2 ll0 = __ldcs(&x[base]);
    float2 ll1 = __ldcs(&x[base + 64]);
    float2 lh0 = __ldcs(&x[base + cs]);
    float2 lh1 = __ldcs(&x[base + cs + 64]);
    float2 hl0 = __ldcs(&x[base + 2 * cs]);
    float2 hl1 = __ldcs(&x[base + 2 * cs + 64]);
    float2 hh0 = __ldcs(&x[base + 3 * cs]);
    float2 hh1 = __ldcs(&x[base + 3 * cs + 64]);

    float4 t0, b0, t1, b1;
    butterfly2(ll0, lh0, hl0, hh0, t0, b0);
    butterfly2(ll1, lh1, hl1, hh1, t1, b1);

    // output: 256 rows * 64 float4/row per (b,c) plane; rows 4r..4r+3
    int o = (bc * 256 + 4 * r) * 64 + j;
    __stcs(&out[o],        t0);
    __stcs(&out[o + 64],   b0);
    __stcs(&out[o + 128],  t1);
    __stcs(&out[o + 192],  b1);
}

extern "C" void kernel_launch(void* const* d_in, const int* in_sizes, int n_in,
                              void* d_out, int out_size)
{
    const float2* x = (const float2*)d_in[0];
    float4* out = (float4*)d_out;

    int total_threads = B * C4 * R * J;  // 8*64*64*64 = 2,097,152
    int block = 256;
    int grid = total_threads / block;    // 8192
    wav_unpack_kernel<<<grid, block>>>(x, out);
}